// round 5
// baseline (speedup 1.0000x reference)
#include <cuda_runtime.h>
#include <math.h>

#define NB 512
#define CD 512
#define SD 49
#define KC 64
#define KTOT 50688        // 25088 (x) + 25088 (t) + 512 (mu)
#define WC_LEN 203
#define G_LEN 1323

// ---- scratch (device globals; no allocation allowed) ----
__device__ float g_Wc[CD * WC_LEN];
__device__ float g_cwT[CD * KC];
__device__ float g_G[G_LEN];
__device__ float g_bias0;
__device__ float g_biasln[SD];
__device__ float g_Bc[KTOT * 64];          // padded so-dim to 64 (zeros beyond 49)
__device__ float g_KT[KTOT * NB];          // [k][n]
__device__ float g_rstd[NB * CD];
__device__ float g_murstd[NB * CD];
__device__ float g_invn[NB * SD];
__device__ float g_cw[NB * SD];
__device__ float g_w2[NB * KC * SD];       // softmax*cw*invn
__device__ float g_ws[NB * KC];            // sum_s softmax*cw
__device__ float g_vlad[NB * KC * CD];

// bilinear 7->20 align_corners matrix element M20[y][a]
__device__ __forceinline__ float m20v(int y, int a) {
    double pos = (double)y * 6.0 / 19.0;
    int lo = (int)floor(pos);
    int hi = lo + 1; if (hi > 6) hi = 6;
    float fr = (float)(pos - (double)lo);
    float v = 0.f;
    if (a == lo) v += 1.f - fr;
    if (a == hi) v += fr;
    return v;
}

// ---------------------------------------------------------------------------
// fold_a: collapse acc_w over conv output channels; transpose conv_w; build G
// ---------------------------------------------------------------------------
__global__ void fold_a(const float* __restrict__ w_s, const float* __restrict__ b_s,
                       const float* __restrict__ w_m, const float* __restrict__ b_m,
                       const float* __restrict__ w_l, const float* __restrict__ b_l,
                       const float* __restrict__ w_t, const float* __restrict__ b_t,
                       const float* __restrict__ acc_w, const float* __restrict__ acc_b,
                       const float* __restrict__ conv_w)
{
    int e = blockIdx.x * blockDim.x + threadIdx.x;
    const int N_WC = CD * WC_LEN;
    const int N_CT = CD * KC;
    if (e < N_WC) {
        int c = e / WC_LEN, r = e % WC_LEN;
        float s = 0.f;
        if (r < 9) {
            for (int o = 0; o < 32; o++) s += acc_w[o] * w_s[(o * CD + c) * 9 + r];
        } else if (r < 58) {
            int r2 = r - 9;
            for (int o = 0; o < 32; o++) s += acc_w[32 + o] * w_m[(o * CD + c) * 49 + r2];
        } else if (r < 139) {
            int r2 = r - 58;
            for (int o = 0; o < 20; o++) s += acc_w[64 + o] * w_l[(o * CD + c) * 81 + r2];
        } else {
            int r2 = r - 139;
            for (int o = 0; o < 16; o++) s += acc_w[84 + o] * w_t[(o * CD + c) * 64 + r2];
        }
        g_Wc[e] = s; return;
    }
    e -= N_WC;
    if (e < N_CT) {
        int c = e / KC, k = e % KC;
        g_cwT[e] = conv_w[k * CD + c];
        return;
    }
    e -= N_CT;
    if (e < G_LEN) {
        int p, io, a, y;
        if (e < 147)      { p = e / 49;           int r = e % 49;          io = r / 7; a = r % 7; y = 3 * io - 1 + p; }
        else if (e < 490) { int t2 = e - 147; p = t2 / 49; int r = t2 % 49; io = r / 7; a = r % 7; y = 5 * io - 9 + p; }
        else if (e < 931) { int t2 = e - 490; p = t2 / 49; int r = t2 % 49; io = r / 7; a = r % 7; y = 2 * io - 1 + p; }
        else              { int t2 = e - 931; p = t2 / 49; int r = t2 % 49; io = r / 7; a = r % 7; y = 2 * io + p; }
        g_G[e] = (y >= 0 && y < 20) ? m20v(y, a) : 0.f;
        return;
    }
    e -= G_LEN;
    if (e < SD) { g_biasln[e] = 0.f; return; }
    e -= SD;
    if (e == 0) {
        float s = acc_b[0];
        for (int o = 0; o < 32; o++) s += acc_w[o]      * b_s[o];
        for (int o = 0; o < 32; o++) s += acc_w[32 + o] * b_m[o];
        for (int o = 0; o < 20; o++) s += acc_w[64 + o] * b_l[o];
        for (int o = 0; o < 16; o++) s += acc_w[84 + o] * b_t[o];
        g_bias0 = s;
    }
}

// ---------------------------------------------------------------------------
// fold_ab: per-channel folded operators A' (ln_w folded), B, A1s, bias_ln
// ---------------------------------------------------------------------------
__global__ void __launch_bounds__(256) fold_ab(const float* __restrict__ ln_w,
                                               const float* __restrict__ ln_b)
{
    __shared__ float sWc[WC_LEN];
    __shared__ float sG[G_LEN];
    __shared__ float sTmp[441];
    __shared__ float sAcc[2401];
    __shared__ float slnw[SD], slnb[SD];
    int c = blockIdx.x, tid = threadIdx.x;
    for (int i = tid; i < WC_LEN; i += 256) sWc[i] = g_Wc[c * WC_LEN + i];
    for (int i = tid; i < G_LEN; i += 256) sG[i] = g_G[i];
    if (tid < SD) { slnw[tid] = ln_w[tid]; slnb[tid] = ln_b[tid]; }
    for (int i = tid; i < 2401; i += 256) sAcc[i] = 0.f;
    __syncthreads();

    const int ksz[4]  = {3, 7, 9, 8};
    const int woff[4] = {0, 9, 58, 139};
    const int goff[4] = {0, 147, 490, 931};

    for (int path = 0; path < 3; path++) {
        int k = ksz[path], wo = woff[path], go = goff[path];
        for (int i = tid; i < k * 49; i += 256) {
            int p = i / 49, jb = i % 49;
            float sum = 0.f;
            for (int q = 0; q < k; q++) sum += sWc[wo + p * k + q] * sG[go + q * 49 + jb];
            sTmp[i] = sum;
        }
        __syncthreads();
        for (int i = tid; i < 2401; i += 256) {
            int si = i / 49, so = i % 49;
            int a = si / 7, b = si % 7, io = so / 7, jo = so % 7;
            float sum = 0.f;
            for (int p = 0; p < k; p++) sum += sG[go + p * 49 + io * 7 + a] * sTmp[p * 49 + jo * 7 + b];
            sAcc[i] += sum;
        }
        __syncthreads();
    }
    // write x-path rows (ln_w folded), padded so-dim to 64
    for (int i = tid; i < 49 * 64; i += 256) {
        int si = i / 64, col = i % 64;
        float v = (col < 49) ? sAcc[si * 49 + col] * slnw[si] : 0.f;
        g_Bc[(c * 49 + si) * 64 + col] = v;
    }
    // A1s rows + bias_ln accumulation
    if (tid < 64) {
        float v = 0.f;
        if (tid < 49) {
            float bl = 0.f;
            for (int si = 0; si < 49; si++) {
                float a = sAcc[si * 49 + tid];
                v  += a * slnw[si];
                bl += a * slnb[si];
            }
            atomicAdd(&g_biasln[tid], bl);
        }
        g_Bc[(50176 + c) * 64 + tid] = v;
    }
    __syncthreads();
    for (int i = tid; i < 2401; i += 256) sAcc[i] = 0.f;
    __syncthreads();
    {   // t path
        int k = 8, wo = woff[3], go = goff[3];
        for (int i = tid; i < k * 49; i += 256) {
            int p = i / 49, jb = i % 49;
            float sum = 0.f;
            for (int q = 0; q < k; q++) sum += sWc[wo + p * k + q] * sG[go + q * 49 + jb];
            sTmp[i] = sum;
        }
        __syncthreads();
        for (int i = tid; i < 2401; i += 256) {
            int si = i / 49, so = i % 49;
            int a = si / 7, b = si % 7, io = so / 7, jo = so % 7;
            float sum = 0.f;
            for (int p = 0; p < k; p++) sum += sG[go + p * 49 + io * 7 + a] * sTmp[p * 49 + jo * 7 + b];
            sAcc[i] += sum;
        }
        __syncthreads();
        for (int i = tid; i < 49 * 64; i += 256) {
            int si = i / 64, col = i % 64;
            float v = (col < 49) ? sAcc[si * 49 + col] : 0.f;
            g_Bc[(25088 + c * 49 + si) * 64 + col] = v;
        }
    }
}

// ---------------------------------------------------------------------------
// cw_init: cw[n][s] = bias0 + bias_ln[s]
// ---------------------------------------------------------------------------
__global__ void cw_init() {
    int i = blockIdx.x * blockDim.x + threadIdx.x;
    if (i < NB * SD) g_cw[i] = g_bias0 + g_biasln[i % SD];
}

// ---------------------------------------------------------------------------
// stats: per (n,c) LayerNorm stats -> rstd, mu*rstd
// ---------------------------------------------------------------------------
__global__ void stats(const float* __restrict__ x) {
    int pair = blockIdx.x * 8 + threadIdx.x / 32;
    int lane = threadIdx.x % 32;
    int n = pair >> 9, c = pair & 511;
    const float* p = x + (size_t)n * 25088 + c * 49;
    float v0 = p[lane];
    float v1 = (lane < 17) ? p[lane + 32] : 0.f;
    float s = v0 + v1;
    float q = v0 * v0 + v1 * v1;
    for (int o = 16; o > 0; o >>= 1) {
        s += __shfl_xor_sync(~0u, s, o);
        q += __shfl_xor_sync(~0u, q, o);
    }
    if (lane == 0) {
        float mu  = s * (1.f / 49.f);
        float var = q * (1.f / 49.f) - mu * mu;
        float rst = rsqrtf(var + 1e-5f);
        g_rstd[n * CD + c]   = rst;
        g_murstd[n * CD + c] = mu * rst;
    }
}

// ---------------------------------------------------------------------------
// transpose-scale: x*rstd and t into KT[k][n]
// ---------------------------------------------------------------------------
__global__ void transpose_xt(const float* __restrict__ x, const float* __restrict__ t) {
    __shared__ float s[32][33];
    int src = blockIdx.z;
    int k0 = blockIdx.x * 32, n0 = blockIdx.y * 32;
    const float* in = src ? t : x;
    int tx = threadIdx.x, ty = threadIdx.y;
    #pragma unroll
    for (int i = 0; i < 4; i++) {
        int n = n0 + ty + 8 * i, k = k0 + tx;
        float v = in[(size_t)n * 25088 + k];
        if (!src) v *= g_rstd[n * CD + k / 49];
        s[ty + 8 * i][tx] = v;
    }
    __syncthreads();
    int rowbase = src ? 25088 : 0;
    #pragma unroll
    for (int i = 0; i < 4; i++) {
        int k = k0 + ty + 8 * i, n = n0 + tx;
        g_KT[(size_t)(rowbase + k) * NB + n] = s[tx][ty + 8 * i];
    }
}

__global__ void fill_mu() {
    int c = blockIdx.x, n = threadIdx.x;
    g_KT[(size_t)(50176 + c) * NB + n] = -g_murstd[n * CD + c];
}

// ---------------------------------------------------------------------------
// cw GEMM: cw[n][so] += sum_k KT[k][n]*Bc[k][so]   (split-K, atomic reduce)
// grid (8 m-tiles, 66 k-chunks of 768), 256 thr, 64x64 tile, 4x4 per thread
// ---------------------------------------------------------------------------
__global__ void __launch_bounds__(256) cw_gemm() {
    __shared__ float sY[8][64], sB[8][64];
    int n0 = blockIdx.x * 64;
    int kbase = blockIdx.y * 768;
    int tid = threadIdx.x;
    int tn = tid % 16, tso = tid / 16;
    float acc[4][4] = {};
    for (int kb = 0; kb < 768; kb += 8) {
        for (int i = tid; i < 512; i += 256) {
            int kk = i / 64, col = i % 64;
            int k = kbase + kb + kk;
            sY[kk][col] = g_KT[(size_t)k * NB + n0 + col];
            sB[kk][col] = g_Bc[k * 64 + col];
        }
        __syncthreads();
        #pragma unroll
        for (int kk = 0; kk < 8; kk++) {
            float4 y4 = *(float4*)&sY[kk][tn * 4];
            float4 b4 = *(float4*)&sB[kk][tso * 4];
            float yv[4] = {y4.x, y4.y, y4.z, y4.w};
            float bv[4] = {b4.x, b4.y, b4.z, b4.w};
            #pragma unroll
            for (int i = 0; i < 4; i++)
                #pragma unroll
                for (int j = 0; j < 4; j++)
                    acc[i][j] += yv[i] * bv[j];
        }
        __syncthreads();
    }
    #pragma unroll
    for (int i = 0; i < 4; i++) {
        int n = n0 + tn * 4 + i;
        #pragma unroll
        for (int j = 0; j < 4; j++) {
            int so = tso * 4 + j;
            if (so < 49) atomicAdd(&g_cw[n * SD + so], acc[i][j]);
        }
    }
}

// ---------------------------------------------------------------------------
// invn: per (n,s) inverse descriptor norm over channels
// ---------------------------------------------------------------------------
__global__ void invn_kernel(const float* __restrict__ x) {
    __shared__ float part[8][64];
    int n = blockIdx.x, w = threadIdx.x / 32, lane = threadIdx.x % 32;
    float a0 = 0.f, a1 = 0.f;
    for (int c = w; c < CD; c += 8) {
        const float* p = x + (size_t)n * 25088 + c * 49;
        float v0 = p[lane]; a0 += v0 * v0;
        if (lane < 17) { float v1 = p[lane + 32]; a1 += v1 * v1; }
    }
    part[w][lane] = a0;
    part[w][32 + lane] = (lane < 17) ? a1 : 0.f;
    __syncthreads();
    if (threadIdx.x < SD) {
        float ss = 0.f;
        for (int ww = 0; ww < 8; ww++) ss += part[ww][threadIdx.x];
        g_invn[n * SD + threadIdx.x] = 1.f / fmaxf(sqrtf(ss), 1e-12f);
    }
}

// ---------------------------------------------------------------------------
// logits + softmax + reweight: per n. Produces w2 = sa*cw*invn, ws = sum_s sa*cw
// ---------------------------------------------------------------------------
__global__ void __launch_bounds__(256) logits_softmax(const float* __restrict__ x,
                                                      const float* __restrict__ conv_b)
{
    __shared__ float sInv[64], sCw[64], sBias[64];
    __shared__ float sW[8][64], sX[8][64];
    __shared__ float sL[64 * 68];
    __shared__ float sP[64 * 68];
    int n = blockIdx.x, tid = threadIdx.x;
    if (tid < 64) {
        sInv[tid]  = (tid < 49) ? g_invn[n * SD + tid] : 0.f;
        sCw[tid]   = (tid < 49) ? g_cw[n * SD + tid] : 0.f;
        sBias[tid] = conv_b[tid];
    }
    __syncthreads();
    int ts = tid % 16, tk = tid / 16;
    float acc[4][4] = {};
    for (int c0 = 0; c0 < CD; c0 += 8) {
        for (int i = tid; i < 512; i += 256) {
            int kk = i / 64, col = i % 64;
            sW[kk][col] = g_cwT[(c0 + kk) * 64 + col];
            sX[kk][col] = (col < 49) ? x[(size_t)n * 25088 + (c0 + kk) * 49 + col] * sInv[col] : 0.f;
        }
        __syncthreads();
        #pragma unroll
        for (int kk = 0; kk < 8; kk++) {
            float4 w4 = *(float4*)&sW[kk][tk * 4];
            float4 x4 = *(float4*)&sX[kk][ts * 4];
            float wv[4] = {w4.x, w4.y, w4.z, w4.w};
            float xv[4] = {x4.x, x4.y, x4.z, x4.w};
            #pragma unroll
            for (int i = 0; i < 4; i++)
                #pragma unroll
                for (int j = 0; j < 4; j++)
                    acc[i][j] += wv[i] * xv[j];
        }
        __syncthreads();
    }
    #pragma unroll
    for (int i = 0; i < 4; i++)
        #pragma unroll
        for (int j = 0; j < 4; j++)
            sL[(tk * 4 + i) * 68 + ts * 4 + j] = acc[i][j] + sBias[tk * 4 + i];
    __syncthreads();
    if (tid < 49) {
        int s = tid;
        float m = -1e30f;
        for (int k = 0; k < KC; k++) m = fmaxf(m, sL[k * 68 + s]);
        float sum = 0.f;
        for (int k = 0; k < KC; k++) {
            float e = __expf(sL[k * 68 + s] - m);
            sL[k * 68 + s] = e; sum += e;
        }
        float f  = sCw[s] / sum;
        float f2 = f * sInv[s];
        for (int k = 0; k < KC; k++) {
            float e = sL[k * 68 + s];
            g_w2[(size_t)n * (KC * SD) + k * SD + s] = e * f2;
            sP[k * 68 + s] = e * f;
        }
    }
    __syncthreads();
    if (tid < KC) {
        float ws = 0.f;
        for (int s = 0; s < SD; s++) ws += sP[tid * 68 + s];
        g_ws[n * KC + tid] = ws;
    }
}

// ---------------------------------------------------------------------------
// vlad GEMM: vlad[n][k][c] = sum_s w2*x - centroids[k][c]*ws[k]
// grid (512 n, 4 c-chunks of 128), 256 thr, 64k x 128c tile, 4x8 per thread
// ---------------------------------------------------------------------------
__global__ void __launch_bounds__(256) vlad_gemm(const float* __restrict__ x,
                                                 const float* __restrict__ centroids)
{
    __shared__ float sw2[49 * 64];   // [s][k]
    __shared__ float sx[49 * 128];   // [s][c]
    __shared__ float sws[64];
    int n = blockIdx.x, c0 = blockIdx.y * 128, tid = threadIdx.x;
    for (int i = tid; i < 3136; i += 256) {
        int k = i / 49, s = i % 49;
        sw2[s * 64 + k] = g_w2[(size_t)n * 3136 + i];
    }
    for (int i = tid; i < 6272; i += 256) {
        int c = i / 49, s = i % 49;
        sx[s * 128 + c] = x[(size_t)n * 25088 + c0 * 49 + i];
    }
    if (tid < 64) sws[tid] = g_ws[n * KC + tid];
    __syncthreads();
    int tk = tid % 16, tc = tid / 16;
    float acc[4][8] = {};
    #pragma unroll 7
    for (int s = 0; s < 49; s++) {
        float4 w4 = *(float4*)&sw2[s * 64 + tk * 4];
        float4 xa = *(float4*)&sx[s * 128 + tc * 8];
        float4 xb = *(float4*)&sx[s * 128 + tc * 8 + 4];
        float wv[4] = {w4.x, w4.y, w4.z, w4.w};
        float xv[8] = {xa.x, xa.y, xa.z, xa.w, xb.x, xb.y, xb.z, xb.w};
        #pragma unroll
        for (int i = 0; i < 4; i++)
            #pragma unroll
            for (int j = 0; j < 8; j++)
                acc[i][j] += wv[i] * xv[j];
    }
    #pragma unroll
    for (int i = 0; i < 4; i++) {
        int k = tk * 4 + i;
        float w = sws[k];
        #pragma unroll
        for (int j = 0; j < 8; j++) {
            int c = c0 + tc * 8 + j;
            g_vlad[(size_t)n * 32768 + k * CD + c] = acc[i][j] - centroids[k * CD + c] * w;
        }
    }
}

// ---------------------------------------------------------------------------
// finalize: intra-norm over c, global norm, write output
// ---------------------------------------------------------------------------
__global__ void __launch_bounds__(512) finalize(float* __restrict__ out) {
    __shared__ float svn[64];
    __shared__ float sred[64];
    __shared__ float sinv[64];
    __shared__ float sg;
    int n = blockIdx.x, tid = threadIdx.x, w = tid / 32, lane = tid % 32;
    const float* v = &g_vlad[(size_t)n * 32768];
    #pragma unroll
    for (int kk = 0; kk < 4; kk++) {
        int k = w + kk * 16;
        float ss = 0.f;
        for (int c = lane * 4; c < CD; c += 128) {
            float4 q = *(const float4*)&v[k * CD + c];
            ss += q.x * q.x + q.y * q.y + q.z * q.z + q.w * q.w;
        }
        for (int o = 16; o > 0; o >>= 1) ss += __shfl_xor_sync(~0u, ss, o);
        if (lane == 0) svn[k] = sqrtf(ss);
    }
    __syncthreads();
    if (tid < 64) {
        float r = svn[tid] / fmaxf(svn[tid], 1e-12f);
        sred[tid] = r * r;
        sinv[tid] = 1.f / fmaxf(svn[tid], 1e-12f);
    }
    __syncthreads();
    if (tid < 32) {
        float ss = sred[tid] + sred[tid + 32];
        for (int o = 16; o > 0; o >>= 1) ss += __shfl_xor_sync(~0u, ss, o);
        if (tid == 0) sg = 1.f / fmaxf(sqrtf(ss), 1e-12f);
    }
    __syncthreads();
    float gi = sg;
    for (int i = tid; i < 32768; i += 512) {
        int k = i >> 9;
        out[(size_t)n * 32768 + i] = v[i] * sinv[k] * gi;
    }
}

// ---------------------------------------------------------------------------
extern "C" void kernel_launch(void* const* d_in, const int* in_sizes, int n_in,
                              void* d_out, int out_size) {
    const float* x         = (const float*)d_in[0];
    const float* t         = (const float*)d_in[1];
    const float* centroids = (const float*)d_in[2];
    const float* conv_w    = (const float*)d_in[3];
    const float* conv_b    = (const float*)d_in[4];
    const float* ln_w      = (const float*)d_in[5];
    const float* ln_b      = (const float*)d_in[6];
    const float* w_t       = (const float*)d_in[7];
    const float* b_t       = (const float*)d_in[8];
    const float* w_s       = (const float*)d_in[9];
    const float* b_s       = (const float*)d_in[10];
    const float* w_m       = (const float*)d_in[11];
    const float* b_m       = (const float*)d_in[12];
    const float* w_l       = (const float*)d_in[13];
    const float* b_l       = (const float*)d_in[14];
    const float* acc_w     = (const float*)d_in[15];
    const float* acc_b     = (const float*)d_in[16];
    float* out = (float*)d_out;

    fold_a<<<540, 256>>>(w_s, b_s, w_m, b_m, w_l, b_l, w_t, b_t, acc_w, acc_b, conv_w);
    fold_ab<<<512, 256>>>(ln_w, ln_b);
    cw_init<<<(NB * SD + 255) / 256, 256>>>();
    stats<<<32768, 256>>>(x);
    fill_mu<<<512, 512>>>();
    {
        dim3 g(784, 16, 2), b(32, 8);
        transpose_xt<<<g, b>>>(x, t);
    }
    {
        dim3 g(8, 66);
        cw_gemm<<<g, 256>>>();
    }
    invn_kernel<<<512, 256>>>(x);
    logits_softmax<<<512, 256>>>(x, conv_b);
    {
        dim3 g(512, 4);
        vlad_gemm<<<g, 256>>>(x, centroids);
    }
    finalize<<<512, 512>>>(out);
}

// round 9
// speedup vs baseline: 1.3378x; 1.3378x over previous
#include <cuda_runtime.h>
#include <math.h>

#define NB 512
#define CD 512
#define SD 49
#define KC 64
#define KTOT 50688        // 25088 (x) + 25088 (t) + 512 (mu)
#define WC_LEN 203
#define G_LEN 1323
#define SXP 513           // padded row stride for [s][c] smem tile

// ---- scratch (device globals; no allocation allowed) ----
__device__ float g_Wc[CD * WC_LEN];
__device__ float g_cwT[CD * KC];
__device__ float g_G[G_LEN];
__device__ float g_bias0;
__device__ float g_biasln[SD];
__device__ float g_Bc[KTOT * 64];          // padded so-dim to 64 (zeros beyond 49)
__device__ float g_xs[NB * CD * SD];       // x * rstd, row-major [n][c*49+s]
__device__ float g_murstd[NB * CD];
__device__ float g_invn[NB * SD];
__device__ float g_cw[NB * SD];
__device__ float g_w2[NB * KC * SD];       // softmax*cw*invn
__device__ float g_ws[NB * KC];            // sum_s softmax*cw

// bilinear 7->20 align_corners matrix element M20[y][a]
__device__ __forceinline__ float m20v(int y, int a) {
    double pos = (double)y * 6.0 / 19.0;
    int lo = (int)floor(pos);
    int hi = lo + 1; if (hi > 6) hi = 6;
    float fr = (float)(pos - (double)lo);
    float v = 0.f;
    if (a == lo) v += 1.f - fr;
    if (a == hi) v += fr;
    return v;
}

// ---------------------------------------------------------------------------
// fold_a: collapse acc_w over conv output channels; transpose conv_w; build G
// ---------------------------------------------------------------------------
__global__ void fold_a(const float* __restrict__ w_s, const float* __restrict__ b_s,
                       const float* __restrict__ w_m, const float* __restrict__ b_m,
                       const float* __restrict__ w_l, const float* __restrict__ b_l,
                       const float* __restrict__ w_t, const float* __restrict__ b_t,
                       const float* __restrict__ acc_w, const float* __restrict__ acc_b,
                       const float* __restrict__ conv_w)
{
    int e = blockIdx.x * blockDim.x + threadIdx.x;
    const int N_WC = CD * WC_LEN;
    const int N_CT = CD * KC;
    if (e < N_WC) {
        int c = e / WC_LEN, r = e % WC_LEN;
        float s = 0.f;
        if (r < 9) {
            for (int o = 0; o < 32; o++) s += acc_w[o] * w_s[(o * CD + c) * 9 + r];
        } else if (r < 58) {
            int r2 = r - 9;
            for (int o = 0; o < 32; o++) s += acc_w[32 + o] * w_m[(o * CD + c) * 49 + r2];
        } else if (r < 139) {
            int r2 = r - 58;
            for (int o = 0; o < 20; o++) s += acc_w[64 + o] * w_l[(o * CD + c) * 81 + r2];
        } else {
            int r2 = r - 139;
            for (int o = 0; o < 16; o++) s += acc_w[84 + o] * w_t[(o * CD + c) * 64 + r2];
        }
        g_Wc[e] = s; return;
    }
    e -= N_WC;
    if (e < N_CT) {
        int c = e / KC, k = e % KC;
        g_cwT[e] = conv_w[k * CD + c];
        return;
    }
    e -= N_CT;
    if (e < G_LEN) {
        int p, io, a, y;
        if (e < 147)      { p = e / 49;           int r = e % 49;          io = r / 7; a = r % 7; y = 3 * io - 1 + p; }
        else if (e < 490) { int t2 = e - 147; p = t2 / 49; int r = t2 % 49; io = r / 7; a = r % 7; y = 5 * io - 9 + p; }
        else if (e < 931) { int t2 = e - 490; p = t2 / 49; int r = t2 % 49; io = r / 7; a = r % 7; y = 2 * io - 1 + p; }
        else              { int t2 = e - 931; p = t2 / 49; int r = t2 % 49; io = r / 7; a = r % 7; y = 2 * io + p; }
        g_G[e] = (y >= 0 && y < 20) ? m20v(y, a) : 0.f;
        return;
    }
    e -= G_LEN;
    if (e < SD) { g_biasln[e] = 0.f; return; }
    e -= SD;
    if (e == 0) {
        float s = acc_b[0];
        for (int o = 0; o < 32; o++) s += acc_w[o]      * b_s[o];
        for (int o = 0; o < 32; o++) s += acc_w[32 + o] * b_m[o];
        for (int o = 0; o < 20; o++) s += acc_w[64 + o] * b_l[o];
        for (int o = 0; o < 16; o++) s += acc_w[84 + o] * b_t[o];
        g_bias0 = s;
    }
}

// ---------------------------------------------------------------------------
// fold_ab: per-channel folded operators A' (ln_w folded), B, A1s, bias_ln
// ---------------------------------------------------------------------------
__global__ void __launch_bounds__(256) fold_ab(const float* __restrict__ ln_w,
                                               const float* __restrict__ ln_b)
{
    __shared__ float sWc[WC_LEN];
    __shared__ float sG[G_LEN];
    __shared__ float sTmp[441];
    __shared__ float sAcc[2401];
    __shared__ float slnw[SD], slnb[SD];
    int c = blockIdx.x, tid = threadIdx.x;
    for (int i = tid; i < WC_LEN; i += 256) sWc[i] = g_Wc[c * WC_LEN + i];
    for (int i = tid; i < G_LEN; i += 256) sG[i] = g_G[i];
    if (tid < SD) { slnw[tid] = ln_w[tid]; slnb[tid] = ln_b[tid]; }
    for (int i = tid; i < 2401; i += 256) sAcc[i] = 0.f;
    __syncthreads();

    const int ksz[4]  = {3, 7, 9, 8};
    const int woff[4] = {0, 9, 58, 139};
    const int goff[4] = {0, 147, 490, 931};

    for (int path = 0; path < 3; path++) {
        int k = ksz[path], wo = woff[path], go = goff[path];
        for (int i = tid; i < k * 49; i += 256) {
            int p = i / 49, jb = i % 49;
            float sum = 0.f;
            for (int q = 0; q < k; q++) sum += sWc[wo + p * k + q] * sG[go + q * 49 + jb];
            sTmp[i] = sum;
        }
        __syncthreads();
        for (int i = tid; i < 2401; i += 256) {
            int si = i / 49, so = i % 49;
            int a = si / 7, b = si % 7, io = so / 7, jo = so % 7;
            float sum = 0.f;
            for (int p = 0; p < k; p++) sum += sG[go + p * 49 + io * 7 + a] * sTmp[p * 49 + jo * 7 + b];
            sAcc[i] += sum;
        }
        __syncthreads();
    }
    // write x-path rows (ln_w folded), padded so-dim to 64
    for (int i = tid; i < 49 * 64; i += 256) {
        int si = i / 64, col = i % 64;
        float v = (col < 49) ? sAcc[si * 49 + col] * slnw[si] : 0.f;
        g_Bc[(c * 49 + si) * 64 + col] = v;
    }
    // A1s rows + bias_ln accumulation
    if (tid < 64) {
        float v = 0.f;
        if (tid < 49) {
            float bl = 0.f;
            for (int si = 0; si < 49; si++) {
                float a = sAcc[si * 49 + tid];
                v  += a * slnw[si];
                bl += a * slnb[si];
            }
            atomicAdd(&g_biasln[tid], bl);
        }
        g_Bc[(50176 + c) * 64 + tid] = v;
    }
    __syncthreads();
    for (int i = tid; i < 2401; i += 256) sAcc[i] = 0.f;
    __syncthreads();
    {   // t path
        int k = 8, wo = woff[3], go = goff[3];
        for (int i = tid; i < k * 49; i += 256) {
            int p = i / 49, jb = i % 49;
            float sum = 0.f;
            for (int q = 0; q < k; q++) sum += sWc[wo + p * k + q] * sG[go + q * 49 + jb];
            sTmp[i] = sum;
        }
        __syncthreads();
        for (int i = tid; i < 2401; i += 256) {
            int si = i / 49, so = i % 49;
            int a = si / 7, b = si % 7, io = so / 7, jo = so % 7;
            float sum = 0.f;
            for (int p = 0; p < k; p++) sum += sG[go + p * 49 + io * 7 + a] * sTmp[p * 49 + jo * 7 + b];
            sAcc[i] += sum;
        }
        __syncthreads();
        for (int i = tid; i < 49 * 64; i += 256) {
            int si = i / 64, col = i % 64;
            float v = (col < 49) ? sAcc[si * 49 + col] : 0.f;
            g_Bc[(25088 + c * 49 + si) * 64 + col] = v;
        }
    }
}

// ---------------------------------------------------------------------------
// cw_init: cw[n][s] = bias0 + bias_ln[s]
// ---------------------------------------------------------------------------
__global__ void cw_init() {
    int i = blockIdx.x * blockDim.x + threadIdx.x;
    if (i < NB * SD) g_cw[i] = g_bias0 + g_biasln[i % SD];
}

// ---------------------------------------------------------------------------
// stats_fused: per n — LayerNorm stats, invn, and xs = x*rstd in ONE pass.
// Block per n, 512 threads, x[n] staged in 100 KB dynamic smem.
// ---------------------------------------------------------------------------
__global__ void __launch_bounds__(512) stats_fused(const float* __restrict__ x) {
    extern __shared__ float sxr[];          // 25088 floats
    __shared__ float srstd[CD];
    int n = blockIdx.x, tid = threadIdx.x, w = tid / 32, lane = tid % 32;
    const float* xr = x + (size_t)n * 25088;
    for (int i = tid; i < 25088; i += 512) sxr[i] = xr[i];
    __syncthreads();
    // per-c LayerNorm stats (warp w handles c = w, w+16, ...)
    for (int j = 0; j < 32; j++) {
        int c = w + 16 * j;
        float v0 = sxr[c * 49 + lane];
        float v1 = (lane < 17) ? sxr[c * 49 + 32 + lane] : 0.f;
        float s = v0 + v1, q = v0 * v0 + v1 * v1;
        for (int o = 16; o > 0; o >>= 1) {
            s += __shfl_xor_sync(~0u, s, o);
            q += __shfl_xor_sync(~0u, q, o);
        }
        if (lane == 0) {
            float mu  = s * (1.f / 49.f);
            float var = q * (1.f / 49.f) - mu * mu;
            float r = rsqrtf(var + 1e-5f);
            srstd[c] = r;
            g_murstd[n * CD + c] = mu * r;
        }
    }
    __syncthreads();
    // invn per s (warp w handles s = w, w+16, w+32)
    for (int j = 0; j < 4; j++) {
        int s = w + 16 * j;
        if (s < SD) {
            float q = 0.f;
            for (int c = lane; c < CD; c += 32) { float v = sxr[c * 49 + s]; q += v * v; }
            for (int o = 16; o > 0; o >>= 1) q += __shfl_xor_sync(~0u, q, o);
            if (lane == 0) g_invn[n * SD + s] = 1.f / fmaxf(sqrtf(q), 1e-12f);
        }
    }
    // xs = x * rstd
    float* xso = g_xs + (size_t)n * 25088;
    for (int i = tid; i < 25088; i += 512) xso[i] = sxr[i] * srstd[i / 49];
}

// ---------------------------------------------------------------------------
// cw GEMM (direct): cw[n][so] += sum_k A[n][k]*Bc[k][so]
// A rows: k<25088 -> xs[n][k]; <50176 -> t[n][k-25088]; else -> -murstd[n][k-50176]
// grid (8 n-tiles, 37 k-splits); 3168 16-k chunks split 86/86/../72; atomics.
// ---------------------------------------------------------------------------
__global__ void __launch_bounds__(256) cw_gemm_direct(const float* __restrict__ t) {
    __shared__ float sA[16][68];
    __shared__ float sB[16][64];
    int n0 = blockIdx.x * 64;
    int cbase = blockIdx.y * 86;
    int ccnt = min(86, 3168 - cbase);
    int tid = threadIdx.x;
    int tn = tid % 16, tso = tid / 16;
    int nn = tid >> 2, kq = (tid & 3) * 4;
    float acc[4][4] = {};
    for (int ch = 0; ch < ccnt; ch++) {
        int k0 = (cbase + ch) * 16;
        {   // A tile: 64n x 16k via float4 (segment-pure: boundaries are 16-aligned)
            const float* base; int col; float sgn = 1.f;
            if (k0 < 25088)      { base = g_xs + (size_t)(n0 + nn) * 25088; col = k0; }
            else if (k0 < 50176) { base = t + (size_t)(n0 + nn) * 25088; col = k0 - 25088; }
            else                 { base = g_murstd + (n0 + nn) * CD; col = k0 - 50176; sgn = -1.f; }
            float4 v = *(const float4*)(base + col + kq);
            sA[kq + 0][nn] = v.x * sgn;
            sA[kq + 1][nn] = v.y * sgn;
            sA[kq + 2][nn] = v.z * sgn;
            sA[kq + 3][nn] = v.w * sgn;
        }
        {   // B tile: 16k x 64so via float4, coalesced
            int kk = tid / 16, s4 = (tid % 16) * 4;
            *(float4*)&sB[kk][s4] = *(const float4*)(g_Bc + (size_t)(k0 + kk) * 64 + s4);
        }
        __syncthreads();
        #pragma unroll
        for (int kk = 0; kk < 16; kk++) {
            float4 y4 = *(float4*)&sA[kk][tn * 4];
            float4 b4 = *(float4*)&sB[kk][tso * 4];
            float yv[4] = {y4.x, y4.y, y4.z, y4.w};
            float bv[4] = {b4.x, b4.y, b4.z, b4.w};
            #pragma unroll
            for (int i = 0; i < 4; i++)
                #pragma unroll
                for (int j = 0; j < 4; j++)
                    acc[i][j] += yv[i] * bv[j];
        }
        __syncthreads();
    }
    #pragma unroll
    for (int i = 0; i < 4; i++) {
        int n = n0 + tn * 4 + i;
        #pragma unroll
        for (int j = 0; j < 4; j++) {
            int so = tso * 4 + j;
            if (so < SD) atomicAdd(&g_cw[n * SD + so], acc[i][j]);
        }
    }
}

// ---------------------------------------------------------------------------
// logits + softmax + reweight: per n. Produces w2 = sa*cw*invn, ws = sum_s sa*cw
// ---------------------------------------------------------------------------
__global__ void __launch_bounds__(256) logits_softmax(const float* __restrict__ x,
                                                      const float* __restrict__ conv_b)
{
    __shared__ float sInv[64], sCw[64], sBias[64];
    __shared__ float sW[8][64], sX[8][64];
    __shared__ float sL[64 * 68];
    __shared__ float sP[64 * 68];
    int n = blockIdx.x, tid = threadIdx.x;
    if (tid < 64) {
        sInv[tid]  = (tid < SD) ? g_invn[n * SD + tid] : 0.f;
        sCw[tid]   = (tid < SD) ? g_cw[n * SD + tid] : 0.f;
        sBias[tid] = conv_b[tid];
    }
    __syncthreads();
    int ts = tid % 16, tk = tid / 16;
    float acc[4][4] = {};
    for (int c0 = 0; c0 < CD; c0 += 8) {
        for (int i = tid; i < 512; i += 256) {
            int kk = i / 64, col = i % 64;
            sW[kk][col] = g_cwT[(c0 + kk) * 64 + col];
            sX[kk][col] = (col < SD) ? x[(size_t)n * 25088 + (c0 + kk) * 49 + col] * sInv[col] : 0.f;
        }
        __syncthreads();
        #pragma unroll
        for (int kk = 0; kk < 8; kk++) {
            float4 w4 = *(float4*)&sW[kk][tk * 4];
            float4 x4 = *(float4*)&sX[kk][ts * 4];
            float wv[4] = {w4.x, w4.y, w4.z, w4.w};
            float xv[4] = {x4.x, x4.y, x4.z, x4.w};
            #pragma unroll
            for (int i = 0; i < 4; i++)
                #pragma unroll
                for (int j = 0; j < 4; j++)
                    acc[i][j] += wv[i] * xv[j];
        }
        __syncthreads();
    }
    #pragma unroll
    for (int i = 0; i < 4; i++)
        #pragma unroll
        for (int j = 0; j < 4; j++)
            sL[(tk * 4 + i) * 68 + ts * 4 + j] = acc[i][j] + sBias[tk * 4 + i];
    __syncthreads();
    if (tid < SD) {
        int s = tid;
        float m = -1e30f;
        for (int k = 0; k < KC; k++) m = fmaxf(m, sL[k * 68 + s]);
        float sum = 0.f;
        for (int k = 0; k < KC; k++) {
            float e = __expf(sL[k * 68 + s] - m);
            sL[k * 68 + s] = e; sum += e;
        }
        float f  = sCw[s] / sum;
        float f2 = f * sInv[s];
        for (int k = 0; k < KC; k++) {
            float e = sL[k * 68 + s];
            g_w2[(size_t)n * (KC * SD) + k * SD + s] = e * f2;
            sP[k * 68 + s] = e * f;
        }
    }
    __syncthreads();
    if (tid < KC) {
        float ws = 0.f;
        for (int s = 0; s < SD; s++) ws += sP[tid * 68 + s];
        g_ws[n * KC + tid] = ws;
    }
}

// ---------------------------------------------------------------------------
// vlad_fused: per n — vlad GEMM + centroid term + intra-norm + global norm +
// output, all in one block (512 threads). x[n] staged in dynamic smem [s][c].
// Thread (tk=tid%16, tc=tid/16): 4 k x 16 c output per thread = full 64x512.
// ---------------------------------------------------------------------------
__global__ void __launch_bounds__(512) vlad_fused(const float* __restrict__ x,
                                                  const float* __restrict__ centroids,
                                                  float* __restrict__ out)
{
    extern __shared__ float sx[];           // 49*SXP floats
    __shared__ float sw2[49 * 64];          // [s][k]
    __shared__ float sws[64];
    __shared__ float snorm[64 * 32];        // [k][tc] partial squared norms
    __shared__ float sred[64], sinv[64];
    __shared__ float sg;
    int n = blockIdx.x, tid = threadIdx.x;
    for (int i = tid; i < 3136; i += 512) {
        int k = i / 49, s = i % 49;
        sw2[s * 64 + k] = g_w2[(size_t)n * 3136 + i];
    }
    for (int i = tid; i < 25088; i += 512) {
        int c = i / 49, s = i % 49;
        sx[s * SXP + c] = x[(size_t)n * 25088 + i];
    }
    if (tid < 64) sws[tid] = g_ws[n * KC + tid];
    __syncthreads();
    int tk = tid % 16, tc = tid / 16;       // tc: 0..31, 16 c each
    float acc[4][16] = {};
    for (int s = 0; s < 49; s++) {
        float4 w4 = *(float4*)&sw2[s * 64 + tk * 4];
        float wv[4] = {w4.x, w4.y, w4.z, w4.w};
        float xv[16];
        #pragma unroll
        for (int j = 0; j < 16; j++) xv[j] = sx[s * SXP + tc * 16 + j];
        #pragma unroll
        for (int i = 0; i < 4; i++)
            #pragma unroll
            for (int j = 0; j < 16; j++)
                acc[i][j] += wv[i] * xv[j];
    }
    // centroid term + partial intra-norms
    #pragma unroll
    for (int i = 0; i < 4; i++) {
        int k = tk * 4 + i;
        float w = sws[k];
        float ss = 0.f;
        #pragma unroll
        for (int j4 = 0; j4 < 4; j4++) {
            float4 cv = *(const float4*)(centroids + (size_t)k * CD + tc * 16 + j4 * 4);
            float cc[4] = {cv.x, cv.y, cv.z, cv.w};
            #pragma unroll
            for (int q = 0; q < 4; q++) {
                int j = j4 * 4 + q;
                acc[i][j] -= cc[q] * w;
                ss += acc[i][j] * acc[i][j];
            }
        }
        snorm[k * 32 + tc] = ss;
    }
    __syncthreads();
    if (tid < 64) {
        float ssum = 0.f;
        for (int u = 0; u < 32; u++) ssum += snorm[tid * 32 + u];
        float vn = sqrtf(ssum);
        float r = vn / fmaxf(vn, 1e-12f);
        sred[tid] = r * r;
        sinv[tid] = 1.f / fmaxf(vn, 1e-12f);
    }
    __syncthreads();
    if (tid < 32) {
        float q = sred[tid] + sred[tid + 32];
        for (int o = 16; o > 0; o >>= 1) q += __shfl_xor_sync(~0u, q, o);
        if (tid == 0) sg = 1.f / fmaxf(sqrtf(q), 1e-12f);
    }
    __syncthreads();
    float gi = sg;
    #pragma unroll
    for (int i = 0; i < 4; i++) {
        int k = tk * 4 + i;
        float f = sinv[k] * gi;
        #pragma unroll
        for (int j4 = 0; j4 < 4; j4++) {
            float4 o4;
            o4.x = acc[i][j4 * 4 + 0] * f;
            o4.y = acc[i][j4 * 4 + 1] * f;
            o4.z = acc[i][j4 * 4 + 2] * f;
            o4.w = acc[i][j4 * 4 + 3] * f;
            *(float4*)(out + (size_t)n * 32768 + (size_t)k * CD + tc * 16 + j4 * 4) = o4;
        }
    }
}

// ---------------------------------------------------------------------------
extern "C" void kernel_launch(void* const* d_in, const int* in_sizes, int n_in,
                              void* d_out, int out_size) {
    const float* x         = (const float*)d_in[0];
    const float* t         = (const float*)d_in[1];
    const float* centroids = (const float*)d_in[2];
    const float* conv_w    = (const float*)d_in[3];
    const float* conv_b    = (const float*)d_in[4];
    const float* ln_w      = (const float*)d_in[5];
    const float* ln_b      = (const float*)d_in[6];
    const float* w_t       = (const float*)d_in[7];
    const float* b_t       = (const float*)d_in[8];
    const float* w_s       = (const float*)d_in[9];
    const float* b_s       = (const float*)d_in[10];
    const float* w_m       = (const float*)d_in[11];
    const float* b_m       = (const float*)d_in[12];
    const float* w_l       = (const float*)d_in[13];
    const float* b_l       = (const float*)d_in[14];
    const float* acc_w     = (const float*)d_in[15];
    const float* acc_b     = (const float*)d_in[16];
    float* out = (float*)d_out;

    cudaFuncSetAttribute(stats_fused, cudaFuncAttributeMaxDynamicSharedMemorySize, 25088 * 4);
    cudaFuncSetAttribute(vlad_fused,  cudaFuncAttributeMaxDynamicSharedMemorySize, 49 * SXP * 4);

    fold_a<<<540, 256>>>(w_s, b_s, w_m, b_m, w_l, b_l, w_t, b_t, acc_w, acc_b, conv_w);
    fold_ab<<<512, 256>>>(ln_w, ln_b);
    cw_init<<<98, 256>>>();
    stats_fused<<<512, 512, 25088 * 4>>>(x);
    {
        dim3 g(8, 37);
        cw_gemm_direct<<<g, 256>>>(t);
    }
    logits_softmax<<<512, 256>>>(x, conv_b);
    vlad_fused<<<512, 512, 49 * SXP * 4>>>(x, centroids, out);
}